// round 3
// baseline (speedup 1.0000x reference)
#include <cuda_runtime.h>
#include <math.h>
#include <stdint.h>

// Problem constants
#define HH 96
#define WWID 96
#define HWSZ (HH * WWID)          // 9216
#define BATCH 8
#define P_TOT (BATCH * HWSZ)      // 73728 pixels
#define C_IN 256
#define C_O 128

// Scratch (device globals — allocation-free per harness rules)
__device__ __align__(16) float g_theta[(size_t)P_TOT * C_O];
__device__ __align__(16) float g_phi  [(size_t)P_TOT * C_O];
__device__ __align__(16) float g_g    [(size_t)P_TOT * C_O];
__device__ __align__(16) float g_wa   [(size_t)P_TOT * C_O];

__device__ __forceinline__ uint32_t f2tf32(float x) {
    uint32_t r;
    asm("cvt.rna.tf32.f32 %0, %1;" : "=r"(r) : "f"(x));
    return r;
}

__device__ __forceinline__ void mma_tf32(float c[4],
                                         uint32_t a0, uint32_t a1, uint32_t a2, uint32_t a3,
                                         uint32_t b0, uint32_t b1) {
    asm volatile(
        "mma.sync.aligned.m16n8k8.row.col.f32.tf32.tf32.f32 "
        "{%0,%1,%2,%3},{%4,%5,%6,%7},{%8,%9},{%0,%1,%2,%3};"
        : "+f"(c[0]), "+f"(c[1]), "+f"(c[2]), "+f"(c[3])
        : "r"(a0), "r"(a1), "r"(a2), "r"(a3), "r"(b0), "r"(b1));
}

__device__ __forceinline__ void ldsm_x4(uint32_t& r0, uint32_t& r1, uint32_t& r2, uint32_t& r3,
                                        uint32_t addr) {
    asm volatile("ldmatrix.sync.aligned.m8n8.x4.shared.b16 {%0,%1,%2,%3}, [%4];"
                 : "=r"(r0), "=r"(r1), "=r"(r2), "=r"(r3) : "r"(addr));
}

__device__ __forceinline__ void ldsm_x2(uint32_t& r0, uint32_t& r1, uint32_t addr) {
    asm volatile("ldmatrix.sync.aligned.m8n8.x2.shared.b16 {%0,%1}, [%2];"
                 : "=r"(r0), "=r"(r1) : "r"(addr));
}

// ---------------------------------------------------------------------------
// Pass 1 (tensor, pipelined): theta/phi/g = W(128x256) @ x_b + bias.
// Tiles 128x128, k-tile 16, double-buffered smem, A frags via ldmatrix.
// A layout: [128 m][20 k-stride]  (m-major; ldmatrix rows = 16B of 4 k-f32)
// B layout: [16 k][136 px-stride]
// grid = (576, 3)
// ---------------------------------------------------------------------------
__global__ __launch_bounds__(256, 2) void pass1_gemm(
    const float* __restrict__ x,
    const float* __restrict__ w_theta, const float* __restrict__ b_theta,
    const float* __restrict__ w_phi,   const float* __restrict__ b_phi,
    const float* __restrict__ w_g,     const float* __restrict__ b_g)
{
    __shared__ __align__(16) float sm[2 * 2560 + 2 * 2176];   // 9472 floats
    float* As = sm;               // [2][128][20]
    float* Bs = sm + 5120;        // [2][16][136]
    float (*stage)[68] = (float(*)[68])sm;

    const int tid = threadIdx.x;
    const int lane = tid & 31;
    const int warp = tid >> 5;
    const int warp_m = warp >> 2;
    const int warp_n = warp & 3;
    const int q = lane >> 2;
    const int kl = lane & 3;

    const int p0 = blockIdx.x * 128;
    const int b = p0 / HWSZ;
    const int hw0 = p0 % HWSZ;
    const int wsel = blockIdx.y;

    const float* wmat = (wsel == 0) ? w_theta : ((wsel == 1) ? w_phi : w_g);
    const float* bias = (wsel == 0) ? b_theta : ((wsel == 1) ? b_phi : b_g);
    float* outp       = (wsel == 0) ? g_theta : ((wsel == 1) ? g_phi : g_g);

    float acc[4][4][4];
#pragma unroll
    for (int mt = 0; mt < 4; ++mt)
#pragma unroll
        for (int nt = 0; nt < 4; ++nt)
#pragma unroll
            for (int i = 0; i < 4; ++i) acc[mt][nt][i] = 0.f;

    const float4* w4 = (const float4*)wmat;   // [128][64]
    const float4* x4 = (const float4*)x;

    // loader mapping
    const int am  = tid >> 1;          // A row (m) / 128
    const int akq = (tid & 1) * 2;     // A k-float4 group
    const int bk0 = tid >> 5;          // B k row (0..7), +8 for second
    const int bpq = tid & 31;          // B px float4

    float4 ra[2], rb[2];

    uint32_t as_u32 = (uint32_t)__cvta_generic_to_shared(As);
    const uint32_t a_base = as_u32 + 4u * ((uint32_t)(warp_m * 64 + (lane & 15)) * 20u
                                           + (uint32_t)(lane >> 4) * 4u);

#define P1_LDG(k0) do { \
    ra[0] = w4[am * (C_IN / 4) + ((k0) >> 2) + akq]; \
    ra[1] = w4[am * (C_IN / 4) + ((k0) >> 2) + akq + 1]; \
    rb[0] = x4[((size_t)(b * C_IN + (k0) + bk0) * HWSZ + hw0) / 4 + bpq]; \
    rb[1] = x4[((size_t)(b * C_IN + (k0) + bk0 + 8) * HWSZ + hw0) / 4 + bpq]; \
} while (0)

#define P1_STS(dst) do { \
    uint4 t0, t1; \
    t0.x = f2tf32(ra[0].x); t0.y = f2tf32(ra[0].y); t0.z = f2tf32(ra[0].z); t0.w = f2tf32(ra[0].w); \
    t1.x = f2tf32(ra[1].x); t1.y = f2tf32(ra[1].y); t1.z = f2tf32(ra[1].z); t1.w = f2tf32(ra[1].w); \
    *(uint4*)&As[(dst) * 2560 + am * 20 + akq * 4]     = t0; \
    *(uint4*)&As[(dst) * 2560 + am * 20 + akq * 4 + 4] = t1; \
    t0.x = f2tf32(rb[0].x); t0.y = f2tf32(rb[0].y); t0.z = f2tf32(rb[0].z); t0.w = f2tf32(rb[0].w); \
    t1.x = f2tf32(rb[1].x); t1.y = f2tf32(rb[1].y); t1.z = f2tf32(rb[1].z); t1.w = f2tf32(rb[1].w); \
    *(uint4*)&Bs[(dst) * 2176 + bk0 * 136 + bpq * 4]       = t0; \
    *(uint4*)&Bs[(dst) * 2176 + (bk0 + 8) * 136 + bpq * 4] = t1; \
} while (0)

    P1_LDG(0);
    P1_STS(0);
    __syncthreads();

#pragma unroll 2
    for (int kt = 0; kt < 16; ++kt) {
        const int buf = kt & 1;
        if (kt < 15) P1_LDG((kt + 1) * 16);

#pragma unroll
        for (int ks = 0; ks < 16; ks += 8) {
            uint32_t af[4][4];
#pragma unroll
            for (int mt = 0; mt < 4; ++mt)
                ldsm_x4(af[mt][0], af[mt][1], af[mt][2], af[mt][3],
                        a_base + (uint32_t)buf * 10240u + (uint32_t)mt * 1280u + (uint32_t)ks * 4u);
            uint32_t bf[4][2];
            const int kq = ks + kl;
#pragma unroll
            for (int nt = 0; nt < 4; ++nt) {
                int pc = warp_n * 32 + nt * 8 + q;
                bf[nt][0] = __float_as_uint(Bs[buf * 2176 + kq * 136 + pc]);
                bf[nt][1] = __float_as_uint(Bs[buf * 2176 + (kq + 4) * 136 + pc]);
            }
#pragma unroll
            for (int mt = 0; mt < 4; ++mt)
#pragma unroll
                for (int nt = 0; nt < 4; ++nt)
                    mma_tf32(acc[mt][nt], af[mt][0], af[mt][1], af[mt][2], af[mt][3],
                             bf[nt][0], bf[nt][1]);
        }

        if (kt < 15) P1_STS(buf ^ 1);
        __syncthreads();
    }
#undef P1_LDG
#undef P1_STS

    // bias per thread-row
    float bias_v[4][2];
#pragma unroll
    for (int mt = 0; mt < 4; ++mt)
#pragma unroll
        for (int hi = 0; hi < 2; ++hi)
            bias_v[mt][hi] = bias[warp_m * 64 + mt * 16 + q + hi * 8];

    // Epilogue: stage in [px][ch] chunks of 64 channels, coalesced stores
#pragma unroll
    for (int h = 0; h < 2; ++h) {
        __syncthreads();
        if (warp_m == h) {
#pragma unroll
            for (int mt = 0; mt < 4; ++mt)
#pragma unroll
                for (int nt = 0; nt < 4; ++nt)
#pragma unroll
                    for (int i = 0; i < 4; ++i) {
                        int px = warp_n * 32 + nt * 8 + 2 * kl + (i & 1);
                        int ch = mt * 16 + q + 8 * (i >> 1);
                        stage[px][ch] = acc[mt][nt][i] + bias_v[mt][i >> 1];
                    }
        }
        __syncthreads();
#pragma unroll
        for (int it = 0; it < 8; ++it) {
            int g = tid + it * 256;
            int px = g >> 4;
            int f  = g & 15;
            float4 v = *(float4*)&stage[px][f * 4];
            ((float4*)outp)[(size_t)(p0 + px) * 32 + h * 16 + f] = v;
        }
    }
}

// ---------------------------------------------------------------------------
// Pass 2: 4 pixels per warp; shared 3x6 neighborhood (phi/g loaded once).
// grid = P_TOT/32, block 256 (8 warps x 4 px).
// ---------------------------------------------------------------------------
__global__ __launch_bounds__(256) void pass2_attn()
{
    const int warp = threadIdx.x >> 5;
    const int lane = threadIdx.x & 31;
    const int grp = blockIdx.x * 8 + warp;
    const int p0 = grp * 4;
    const int b  = p0 / HWSZ;
    const int hw = p0 % HWSZ;
    const int h  = hw / WWID;
    const int w0 = hw % WWID;

    const float4* th4 = (const float4*)g_theta;
    const float4* ph4 = (const float4*)g_phi;
    const float4* gg4 = (const float4*)g_g;

    float4 th[4];
    float tn[4];
#pragma unroll
    for (int j = 0; j < 4; ++j) {
        th[j] = th4[(size_t)(p0 + j) * 32 + lane];
        float tt = th[j].x * th[j].x + th[j].y * th[j].y
                 + th[j].z * th[j].z + th[j].w * th[j].w;
#pragma unroll
        for (int off = 16; off; off >>= 1)
            tt += __shfl_xor_sync(0xffffffffu, tt, off);
        tn[j] = sqrtf(tt);
    }

    float sc[4][9];
#pragma unroll
    for (int r = 0; r < 3; ++r) {
        int hr = min(max(h - 1 + r, 0), HH - 1);
        int rowb = b * HWSZ + hr * WWID;
#pragma unroll
        for (int c = 0; c < 6; ++c) {
            int wc = min(max(w0 - 1 + c, 0), WWID - 1);
            int np = rowb + wc;
            float4 ph = ph4[(size_t)np * 32 + lane];
            float pp = ph.x * ph.x + ph.y * ph.y + ph.z * ph.z + ph.w * ph.w;
            const int j0 = (c - 2 > 0) ? c - 2 : 0;
            const int j1 = (c < 3) ? c : 3;
            float dv[3];
#pragma unroll
            for (int t = 0; t < 3; ++t) {
                if (t <= j1 - j0) {
                    int j = j0 + t;
                    dv[t] = th[j].x * ph.x + th[j].y * ph.y
                          + th[j].z * ph.z + th[j].w * ph.w;
                }
            }
#pragma unroll
            for (int off = 16; off; off >>= 1) {
                pp += __shfl_xor_sync(0xffffffffu, pp, off);
#pragma unroll
                for (int t = 0; t < 3; ++t)
                    if (t <= j1 - j0)
                        dv[t] += __shfl_xor_sync(0xffffffffu, dv[t], off);
            }
            float pn = sqrtf(pp);
#pragma unroll
            for (int t = 0; t < 3; ++t) {
                if (t <= j1 - j0) {
                    int j = j0 + t;
                    sc[j][r * 3 + (c - j)] = dv[t] / fmaxf(tn[j] * pn, 1e-8f);
                }
            }
        }
    }

    // softmax per pixel (per-lane redundant)
#pragma unroll
    for (int j = 0; j < 4; ++j) {
        float m = sc[j][0];
#pragma unroll
        for (int n = 1; n < 9; ++n) m = fmaxf(m, sc[j][n]);
        float s = 0.f;
#pragma unroll
        for (int n = 0; n < 9; ++n) { sc[j][n] = __expf(sc[j][n] - m); s += sc[j][n]; }
        float inv = 1.f / s;
#pragma unroll
        for (int n = 0; n < 9; ++n) sc[j][n] *= inv;
    }

    float4 acc[4];
#pragma unroll
    for (int j = 0; j < 4; ++j) acc[j] = make_float4(0.f, 0.f, 0.f, 0.f);

#pragma unroll
    for (int r = 0; r < 3; ++r) {
        int hr = min(max(h - 1 + r, 0), HH - 1);
        int rowb = b * HWSZ + hr * WWID;
#pragma unroll
        for (int c = 0; c < 6; ++c) {
            int wc = min(max(w0 - 1 + c, 0), WWID - 1);
            int np = rowb + wc;
            float4 gv = gg4[(size_t)np * 32 + lane];
            const int j0 = (c - 2 > 0) ? c - 2 : 0;
            const int j1 = (c < 3) ? c : 3;
#pragma unroll
            for (int j = 0; j < 4; ++j) {
                if (j >= j0 && j <= j1) {
                    float a = sc[j][r * 3 + (c - j)];
                    acc[j].x += a * gv.x; acc[j].y += a * gv.y;
                    acc[j].z += a * gv.z; acc[j].w += a * gv.w;
                }
            }
        }
    }
#pragma unroll
    for (int j = 0; j < 4; ++j)
        ((float4*)g_wa)[(size_t)(p0 + j) * 32 + lane] = acc[j];
}

// ---------------------------------------------------------------------------
// Pass 3 (tensor, pipelined): out = x + W_back(256x128) @ wa + b_back.
// A layout [128 c][20], B layout [128 px][20]; both frag-loaded via ldmatrix.
// grid = (576, 2)
// ---------------------------------------------------------------------------
__global__ __launch_bounds__(256, 2) void pass3_gemm(
    const float* __restrict__ x,
    const float* __restrict__ w_back, const float* __restrict__ b_back,
    float* __restrict__ out)
{
    __shared__ __align__(16) float sm[2 * 2560 + 2 * 2560];   // 10240 floats
    float* As = sm;               // [2][128][20]
    float* Bs = sm + 5120;        // [2][128][20]
    float (*stage)[132] = (float(*)[132])sm;

    const int tid = threadIdx.x;
    const int lane = tid & 31;
    const int warp = tid >> 5;
    const int warp_m = warp >> 2;
    const int warp_n = warp & 3;
    const int q = lane >> 2;
    const int kl = lane & 3;

    const int p0 = blockIdx.x * 128;
    const int b = p0 / HWSZ;
    const int hw0 = p0 % HWSZ;
    const int c0 = blockIdx.y * 128;

    float acc[4][4][4];
#pragma unroll
    for (int mt = 0; mt < 4; ++mt)
#pragma unroll
        for (int nt = 0; nt < 4; ++nt)
#pragma unroll
            for (int i = 0; i < 4; ++i) acc[mt][nt][i] = 0.f;

    const float4* w4  = (const float4*)w_back;   // [256][32]
    const float4* wa4 = (const float4*)g_wa;     // [P][32]

    const int am  = tid >> 1;
    const int akq = (tid & 1) * 2;

    float4 ra[2], rb[2];

    uint32_t as_u32 = (uint32_t)__cvta_generic_to_shared(As);
    uint32_t bs_u32 = (uint32_t)__cvta_generic_to_shared(Bs);
    const uint32_t a_base = as_u32 + 4u * ((uint32_t)(warp_m * 64 + (lane & 15)) * 20u
                                           + (uint32_t)(lane >> 4) * 4u);
    const uint32_t b_base = bs_u32 + 4u * ((uint32_t)(warp_n * 32 + (lane & 7)) * 20u
                                           + (uint32_t)((lane >> 3) & 1) * 4u);

#define P3_LDG(k0) do { \
    ra[0] = w4[(size_t)(c0 + am) * (C_O / 4) + ((k0) >> 2) + akq]; \
    ra[1] = w4[(size_t)(c0 + am) * (C_O / 4) + ((k0) >> 2) + akq + 1]; \
    rb[0] = wa4[(size_t)(p0 + am) * (C_O / 4) + ((k0) >> 2) + akq]; \
    rb[1] = wa4[(size_t)(p0 + am) * (C_O / 4) + ((k0) >> 2) + akq + 1]; \
} while (0)

#define P3_STS(dst) do { \
    uint4 t0, t1; \
    t0.x = f2tf32(ra[0].x); t0.y = f2tf32(ra[0].y); t0.z = f2tf32(ra[0].z); t0.w = f2tf32(ra[0].w); \
    t1.x = f2tf32(ra[1].x); t1.y = f2tf32(ra[1].y); t1.z = f2tf32(ra[1].z); t1.w = f2tf32(ra[1].w); \
    *(uint4*)&As[(dst) * 2560 + am * 20 + akq * 4]     = t0; \
    *(uint4*)&As[(dst) * 2560 + am * 20 + akq * 4 + 4] = t1; \
    t0.x = f2tf32(rb[0].x); t0.y = f2tf32(rb[0].y); t0.z = f2tf32(rb[0].z); t0.w = f2tf32(rb[0].w); \
    t1.x = f2tf32(rb[1].x); t1.y = f2tf32(rb[1].y); t1.z = f2tf32(rb[1].z); t1.w = f2tf32(rb[1].w); \
    *(uint4*)&Bs[(dst) * 2560 + am * 20 + akq * 4]     = t0; \
    *(uint4*)&Bs[(dst) * 2560 + am * 20 + akq * 4 + 4] = t1; \
} while (0)

    P3_LDG(0);
    P3_STS(0);
    __syncthreads();

#pragma unroll 2
    for (int kt = 0; kt < 8; ++kt) {
        const int buf = kt & 1;
        if (kt < 7) P3_LDG((kt + 1) * 16);

#pragma unroll
        for (int ks = 0; ks < 16; ks += 8) {
            uint32_t af[4][4];
#pragma unroll
            for (int mt = 0; mt < 4; ++mt)
                ldsm_x4(af[mt][0], af[mt][1], af[mt][2], af[mt][3],
                        a_base + (uint32_t)buf * 10240u + (uint32_t)mt * 1280u + (uint32_t)ks * 4u);
            uint32_t bf[4][2];
#pragma unroll
            for (int nt = 0; nt < 4; ++nt)
                ldsm_x2(bf[nt][0], bf[nt][1],
                        b_base + (uint32_t)buf * 10240u + (uint32_t)nt * 640u + (uint32_t)ks * 4u);
#pragma unroll
            for (int mt = 0; mt < 4; ++mt)
#pragma unroll
                for (int nt = 0; nt < 4; ++nt)
                    mma_tf32(acc[mt][nt], af[mt][0], af[mt][1], af[mt][2], af[mt][3],
                             bf[nt][0], bf[nt][1]);
        }

        if (kt < 7) P3_STS(buf ^ 1);
        __syncthreads();
    }
#undef P3_LDG
#undef P3_STS

    // Epilogue: stage [ch][px], then coalesced residual-add + store
#pragma unroll
    for (int h = 0; h < 2; ++h) {
        __syncthreads();
        if (warp_m == h) {
#pragma unroll
            for (int mt = 0; mt < 4; ++mt)
#pragma unroll
                for (int nt = 0; nt < 4; ++nt)
#pragma unroll
                    for (int hi = 0; hi < 2; ++hi) {
                        int ch = mt * 16 + q + 8 * hi;
                        int px = warp_n * 32 + nt * 8 + 2 * kl;
                        float2 v2 = make_float2(acc[mt][nt][hi * 2], acc[mt][nt][hi * 2 + 1]);
                        *(float2*)&stage[ch][px] = v2;
                    }
        }
        __syncthreads();
#pragma unroll
        for (int it = 0; it < 8; ++it) {
            int g = tid + it * 256;
            int ch = g >> 5;
            int f  = g & 31;
            int c  = c0 + h * 64 + ch;
            size_t gi = (((size_t)(b * C_IN + c)) * HWSZ + hw0) / 4 + f;
            float4 s = *(float4*)&stage[ch][f * 4];
            float4 xv = ((const float4*)x)[gi];
            float bb = b_back[c];
            float4 o4;
            o4.x = xv.x + bb + s.x;
            o4.y = xv.y + bb + s.y;
            o4.z = xv.z + bb + s.z;
            o4.w = xv.w + bb + s.w;
            ((float4*)out)[gi] = o4;
        }
    }
}

// ---------------------------------------------------------------------------
extern "C" void kernel_launch(void* const* d_in, const int* in_sizes, int n_in,
                              void* d_out, int out_size)
{
    const float* x       = (const float*)d_in[0];
    const float* w_theta = (const float*)d_in[1];
    const float* b_theta = (const float*)d_in[2];
    const float* w_phi   = (const float*)d_in[3];
    const float* b_phi   = (const float*)d_in[4];
    const float* w_g     = (const float*)d_in[5];
    const float* b_g     = (const float*)d_in[6];
    const float* w_back  = (const float*)d_in[7];
    const float* b_back  = (const float*)d_in[8];
    float* out = (float*)d_out;

    dim3 g1(P_TOT / 128, 3, 1);
    pass1_gemm<<<g1, 256>>>(x, w_theta, b_theta, w_phi, b_phi, w_g, b_g);

    pass2_attn<<<P_TOT / 32, 256>>>();

    dim3 g3(P_TOT / 128, 2, 1);
    pass3_gemm<<<g3, 256>>>(x, w_back, b_back, out);
}

// round 4
// speedup vs baseline: 1.1345x; 1.1345x over previous
#include <cuda_runtime.h>
#include <math.h>
#include <stdint.h>

// Problem constants
#define HH 96
#define WWID 96
#define HWSZ (HH * WWID)          // 9216
#define BATCH 8
#define P_TOT (BATCH * HWSZ)      // 73728 pixels
#define C_IN 256
#define C_O 128

// Scratch (device globals — allocation-free per harness rules)
__device__ __align__(16) float g_theta[(size_t)P_TOT * C_O];
__device__ __align__(16) float g_phi  [(size_t)P_TOT * C_O];
__device__ __align__(16) float g_g    [(size_t)P_TOT * C_O];
__device__ __align__(16) float g_wa   [(size_t)P_TOT * C_O];   // stored tf32-rounded
__device__ __align__(16) float g_w3   [3 * C_O * C_IN];        // tf32 w_theta|w_phi|w_g
__device__ __align__(16) float g_wb   [C_IN * C_O];            // tf32 w_back

__device__ __forceinline__ uint32_t f2tf32(float x) {
    uint32_t r;
    asm("cvt.rna.tf32.f32 %0, %1;" : "=r"(r) : "f"(x));
    return r;
}

__device__ __forceinline__ void mma_tf32(float c[4],
                                         uint32_t a0, uint32_t a1, uint32_t a2, uint32_t a3,
                                         uint32_t b0, uint32_t b1) {
    asm volatile(
        "mma.sync.aligned.m16n8k8.row.col.f32.tf32.tf32.f32 "
        "{%0,%1,%2,%3},{%4,%5,%6,%7},{%8,%9},{%0,%1,%2,%3};"
        : "+f"(c[0]), "+f"(c[1]), "+f"(c[2]), "+f"(c[3])
        : "r"(a0), "r"(a1), "r"(a2), "r"(a3), "r"(b0), "r"(b1));
}

__device__ __forceinline__ void ldsm_x4(uint32_t& r0, uint32_t& r1, uint32_t& r2, uint32_t& r3,
                                        uint32_t addr) {
    asm volatile("ldmatrix.sync.aligned.m8n8.x4.shared.b16 {%0,%1,%2,%3}, [%4];"
                 : "=r"(r0), "=r"(r1), "=r"(r2), "=r"(r3) : "r"(addr));
}

__device__ __forceinline__ void ldsm_x2(uint32_t& r0, uint32_t& r1, uint32_t addr) {
    asm volatile("ldmatrix.sync.aligned.m8n8.x2.shared.b16 {%0,%1}, [%2];"
                 : "=r"(r0), "=r"(r1) : "r"(addr));
}

#define CP16_CA(dst, src) \
    asm volatile("cp.async.ca.shared.global [%0], [%1], 16;" :: "r"(dst), "l"(src))
#define CP16_CG(dst, src) \
    asm volatile("cp.async.cg.shared.global [%0], [%1], 16;" :: "r"(dst), "l"(src))
#define CP_COMMIT() asm volatile("cp.async.commit_group;")
#define CP_WAIT0()  asm volatile("cp.async.wait_group 0;")

// ---------------------------------------------------------------------------
// Setup: tf32-round all weights once.
// ---------------------------------------------------------------------------
__global__ void cvt_weights(const float* __restrict__ wt, const float* __restrict__ wp,
                            const float* __restrict__ wg, const float* __restrict__ wb)
{
    int i = blockIdx.x * 256 + threadIdx.x;      // 0 .. 32767
    g_w3[i]              = __uint_as_float(f2tf32(wt[i]));
    g_w3[32768 + i]      = __uint_as_float(f2tf32(wp[i]));
    g_w3[65536 + i]      = __uint_as_float(f2tf32(wg[i]));
    g_wb[i]              = __uint_as_float(f2tf32(wb[i]));
}

// ---------------------------------------------------------------------------
// Pass 1 (tensor, cp.async pipelined): theta/phi/g = W(128x256) @ x_b + bias.
// A smem: [128 m][20] (ldsm), B smem: [16 k][136 px] (LDS broadcast, raw fp32 —
// HW truncates to tf32 inside the MMA). grid = (576, 3).
// ---------------------------------------------------------------------------
__global__ __launch_bounds__(256, 2) void pass1_gemm(
    const float* __restrict__ x,
    const float* __restrict__ b_theta, const float* __restrict__ b_phi,
    const float* __restrict__ b_g)
{
    __shared__ __align__(16) float sm[2 * 2560 + 2 * 2176];   // 9472 floats
    float* As = sm;               // [2][128][20]
    float* Bs = sm + 5120;        // [2][16][136]
    float (*stage)[68] = (float(*)[68])sm;

    const int tid = threadIdx.x;
    const int lane = tid & 31;
    const int warp = tid >> 5;
    const int warp_m = warp >> 2;
    const int warp_n = warp & 3;
    const int q = lane >> 2;
    const int kl = lane & 3;

    const int p0 = blockIdx.x * 128;
    const int b = p0 / HWSZ;
    const int hw0 = p0 % HWSZ;
    const int wsel = blockIdx.y;

    const float* wsrc = g_w3 + wsel * 32768;
    const float* bias = (wsel == 0) ? b_theta : ((wsel == 1) ? b_phi : b_g);
    float* outp       = (wsel == 0) ? g_theta : ((wsel == 1) ? g_phi : g_g);

    float acc[4][4][4];
#pragma unroll
    for (int mt = 0; mt < 4; ++mt)
#pragma unroll
        for (int nt = 0; nt < 4; ++nt)
#pragma unroll
            for (int i = 0; i < 4; ++i) acc[mt][nt][i] = 0.f;

    // loader mapping (32B contiguous per thread per tile side)
    const int am   = tid >> 1;            // A row m
    const int akq0 = (tid & 1) * 2;       // A k-float4 group
    const int bk   = tid >> 4;            // B k row
    const int bpq0 = (tid & 15) * 2;      // B px-float4 group

    const uint32_t as_base = (uint32_t)__cvta_generic_to_shared(As);
    const uint32_t bs_base = (uint32_t)__cvta_generic_to_shared(Bs);
    const uint32_t a_dst0 = as_base + 4u * (uint32_t)(am * 20 + akq0 * 4);
    const uint32_t b_dst0 = bs_base + 4u * (uint32_t)(bk * 136 + bpq0 * 4);
    const float* a_src0 = wsrc + am * C_IN + akq0 * 4;
    const float* b_src0 = x + (size_t)(b * C_IN + bk) * HWSZ + hw0 + bpq0 * 4;

    const uint32_t a_frag = as_base + 4u * ((uint32_t)(warp_m * 64 + (lane & 15)) * 20u
                                            + (uint32_t)(lane >> 4) * 4u);

#define P1_ISSUE(buf, k0) do { \
    const float* as_ = a_src0 + (k0); \
    uint32_t ad_ = a_dst0 + (uint32_t)(buf) * 10240u; \
    CP16_CA(ad_,      as_); \
    CP16_CA(ad_ + 16, as_ + 4); \
    const float* bs_ = b_src0 + (size_t)(k0) * HWSZ; \
    uint32_t bd_ = b_dst0 + (uint32_t)(buf) * 8704u; \
    CP16_CG(bd_,      bs_); \
    CP16_CG(bd_ + 16, bs_ + 4); \
} while (0)

    P1_ISSUE(0, 0);
    CP_COMMIT();
    CP_WAIT0();
    __syncthreads();

#pragma unroll 2
    for (int kt = 0; kt < 16; ++kt) {
        const int buf = kt & 1;
        if (kt < 15) { P1_ISSUE(buf ^ 1, (kt + 1) * 16); CP_COMMIT(); }

#pragma unroll
        for (int ks = 0; ks < 16; ks += 8) {
            uint32_t af[4][4];
#pragma unroll
            for (int mt = 0; mt < 4; ++mt)
                ldsm_x4(af[mt][0], af[mt][1], af[mt][2], af[mt][3],
                        a_frag + (uint32_t)buf * 10240u + (uint32_t)mt * 1280u + (uint32_t)ks * 4u);
            uint32_t bf[4][2];
            const int kq = ks + kl;
#pragma unroll
            for (int nt = 0; nt < 4; ++nt) {
                int pc = warp_n * 32 + nt * 8 + q;
                bf[nt][0] = __float_as_uint(Bs[buf * 2176 + kq * 136 + pc]);
                bf[nt][1] = __float_as_uint(Bs[buf * 2176 + (kq + 4) * 136 + pc]);
            }
#pragma unroll
            for (int mt = 0; mt < 4; ++mt)
#pragma unroll
                for (int nt = 0; nt < 4; ++nt)
                    mma_tf32(acc[mt][nt], af[mt][0], af[mt][1], af[mt][2], af[mt][3],
                             bf[nt][0], bf[nt][1]);
        }

        if (kt < 15) CP_WAIT0();
        __syncthreads();
    }
#undef P1_ISSUE

    // bias per thread-row
    float bias_v[4][2];
#pragma unroll
    for (int mt = 0; mt < 4; ++mt)
#pragma unroll
        for (int hi = 0; hi < 2; ++hi)
            bias_v[mt][hi] = bias[warp_m * 64 + mt * 16 + q + hi * 8];

    // Epilogue: stage in [px][ch] chunks of 64 channels, coalesced stores
#pragma unroll
    for (int h = 0; h < 2; ++h) {
        __syncthreads();
        if (warp_m == h) {
#pragma unroll
            for (int mt = 0; mt < 4; ++mt)
#pragma unroll
                for (int nt = 0; nt < 4; ++nt)
#pragma unroll
                    for (int i = 0; i < 4; ++i) {
                        int px = warp_n * 32 + nt * 8 + 2 * kl + (i & 1);
                        int ch = mt * 16 + q + 8 * (i >> 1);
                        stage[px][ch] = acc[mt][nt][i] + bias_v[mt][i >> 1];
                    }
        }
        __syncthreads();
#pragma unroll
        for (int it = 0; it < 8; ++it) {
            int g = tid + it * 256;
            int px = g >> 4;
            int f  = g & 15;
            float4 v = *(float4*)&stage[px][f * 4];
            ((float4*)outp)[(size_t)(p0 + px) * 32 + h * 16 + f] = v;
        }
    }
}

// ---------------------------------------------------------------------------
// Pass 2: per-pixel 3x3 cosine-sim softmax + weighted avg of g (warp/pixel).
// wa stored tf32-rounded for pass3's raw cp.async consumption.
// ---------------------------------------------------------------------------
__global__ __launch_bounds__(256) void pass2_attn()
{
    const int warp = threadIdx.x >> 5;
    const int lane = threadIdx.x & 31;
    const int p = blockIdx.x * 8 + warp;
    const int b  = p / HWSZ;
    const int hw = p % HWSZ;
    const int h = hw / WWID;
    const int w = hw % WWID;

    const float4* th4 = (const float4*)g_theta;
    const float4* ph4 = (const float4*)g_phi;
    const float4* gg4 = (const float4*)g_g;

    float4 th = th4[(size_t)p * 32 + lane];

    float tt = th.x * th.x + th.y * th.y + th.z * th.z + th.w * th.w;
#pragma unroll
    for (int off = 16; off; off >>= 1)
        tt += __shfl_xor_sync(0xffffffffu, tt, off);
    float tn = sqrtf(tt);

    int pn[9];
    float sc[9];
#pragma unroll
    for (int n = 0; n < 9; ++n) {
        int di = n / 3 - 1, dj = n % 3 - 1;
        int hh = min(max(h + di, 0), HH - 1);
        int wn = min(max(w + dj, 0), WWID - 1);
        pn[n] = b * HWSZ + hh * WWID + wn;
        float4 ph = ph4[(size_t)pn[n] * 32 + lane];
        float d  = th.x * ph.x + th.y * ph.y + th.z * ph.z + th.w * ph.w;
        float pp = ph.x * ph.x + ph.y * ph.y + ph.z * ph.z + ph.w * ph.w;
#pragma unroll
        for (int off = 16; off; off >>= 1) {
            d  += __shfl_xor_sync(0xffffffffu, d, off);
            pp += __shfl_xor_sync(0xffffffffu, pp, off);
        }
        float den = fmaxf(tn * sqrtf(pp), 1e-8f);
        sc[n] = d / den;
    }
    // softmax over 9 (scores bounded in [-1,1]: no max-shift needed)
    float s = 0.f;
#pragma unroll
    for (int n = 0; n < 9; ++n) { sc[n] = __expf(sc[n]); s += sc[n]; }
    float inv = 1.f / s;

    float4 acc = make_float4(0.f, 0.f, 0.f, 0.f);
#pragma unroll
    for (int n = 0; n < 9; ++n) {
        float a = sc[n] * inv;
        float4 gv = gg4[(size_t)pn[n] * 32 + lane];
        acc.x += a * gv.x; acc.y += a * gv.y;
        acc.z += a * gv.z; acc.w += a * gv.w;
    }
    uint4 o;
    o.x = f2tf32(acc.x); o.y = f2tf32(acc.y);
    o.z = f2tf32(acc.z); o.w = f2tf32(acc.w);
    ((uint4*)g_wa)[(size_t)p * 32 + lane] = o;
}

// ---------------------------------------------------------------------------
// Pass 3 (tensor, cp.async pipelined): out = x + W_back(256x128) @ wa + b_back.
// A smem [128 c][20], B smem [128 px][20]; both via ldmatrix. grid = (576, 2).
// ---------------------------------------------------------------------------
__global__ __launch_bounds__(256, 2) void pass3_gemm(
    const float* __restrict__ x,
    const float* __restrict__ b_back,
    float* __restrict__ out)
{
    __shared__ __align__(16) float sm[2 * 2560 + 2 * 2560];   // 10240 floats
    float* As = sm;               // [2][128][20]
    float* Bs = sm + 5120;        // [2][128][20]
    float (*stage)[132] = (float(*)[132])sm;

    const int tid = threadIdx.x;
    const int lane = tid & 31;
    const int warp = tid >> 5;
    const int warp_m = warp >> 2;
    const int warp_n = warp & 3;
    const int q = lane >> 2;
    const int kl = lane & 3;

    const int p0 = blockIdx.x * 128;
    const int b = p0 / HWSZ;
    const int hw0 = p0 % HWSZ;
    const int c0 = blockIdx.y * 128;

    float acc[4][4][4];
#pragma unroll
    for (int mt = 0; mt < 4; ++mt)
#pragma unroll
        for (int nt = 0; nt < 4; ++nt)
#pragma unroll
            for (int i = 0; i < 4; ++i) acc[mt][nt][i] = 0.f;

    const int am   = tid >> 1;
    const int akq0 = (tid & 1) * 2;

    const uint32_t as_base = (uint32_t)__cvta_generic_to_shared(As);
    const uint32_t bs_base = (uint32_t)__cvta_generic_to_shared(Bs);
    const uint32_t a_dst0 = as_base + 4u * (uint32_t)(am * 20 + akq0 * 4);
    const uint32_t b_dst0 = bs_base + 4u * (uint32_t)(am * 20 + akq0 * 4);
    const float* a_src0 = g_wb + (size_t)(c0 + am) * C_O + akq0 * 4;
    const float* b_src0 = g_wa + (size_t)(p0 + am) * C_O + akq0 * 4;

    const uint32_t a_frag = as_base + 4u * ((uint32_t)(warp_m * 64 + (lane & 15)) * 20u
                                            + (uint32_t)(lane >> 4) * 4u);
    const uint32_t b_frag = bs_base + 4u * ((uint32_t)(warp_n * 32 + (lane & 7)) * 20u
                                            + (uint32_t)((lane >> 3) & 1) * 4u);

#define P3_ISSUE(buf, k0) do { \
    const float* as_ = a_src0 + (k0); \
    uint32_t ad_ = a_dst0 + (uint32_t)(buf) * 10240u; \
    CP16_CA(ad_,      as_); \
    CP16_CA(ad_ + 16, as_ + 4); \
    const float* bs_ = b_src0 + (k0); \
    uint32_t bd_ = b_dst0 + (uint32_t)(buf) * 10240u; \
    CP16_CG(bd_,      bs_); \
    CP16_CG(bd_ + 16, bs_ + 4); \
} while (0)

    P3_ISSUE(0, 0);
    CP_COMMIT();
    CP_WAIT0();
    __syncthreads();

#pragma unroll 2
    for (int kt = 0; kt < 8; ++kt) {
        const int buf = kt & 1;
        if (kt < 7) { P3_ISSUE(buf ^ 1, (kt + 1) * 16); CP_COMMIT(); }

#pragma unroll
        for (int ks = 0; ks < 16; ks += 8) {
            uint32_t af[4][4];
#pragma unroll
            for (int mt = 0; mt < 4; ++mt)
                ldsm_x4(af[mt][0], af[mt][1], af[mt][2], af[mt][3],
                        a_frag + (uint32_t)buf * 10240u + (uint32_t)mt * 1280u + (uint32_t)ks * 4u);
            uint32_t bf[4][2];
#pragma unroll
            for (int nt = 0; nt < 4; ++nt)
                ldsm_x2(bf[nt][0], bf[nt][1],
                        b_frag + (uint32_t)buf * 10240u + (uint32_t)nt * 640u + (uint32_t)ks * 4u);
#pragma unroll
            for (int mt = 0; mt < 4; ++mt)
#pragma unroll
                for (int nt = 0; nt < 4; ++nt)
                    mma_tf32(acc[mt][nt], af[mt][0], af[mt][1], af[mt][2], af[mt][3],
                             bf[nt][0], bf[nt][1]);
        }

        if (kt < 7) CP_WAIT0();
        __syncthreads();
    }
#undef P3_ISSUE

    // Epilogue: stage [ch][px], then coalesced residual-add + store
#pragma unroll
    for (int h = 0; h < 2; ++h) {
        __syncthreads();
        if (warp_m == h) {
#pragma unroll
            for (int mt = 0; mt < 4; ++mt)
#pragma unroll
                for (int nt = 0; nt < 4; ++nt)
#pragma unroll
                    for (int hi = 0; hi < 2; ++hi) {
                        int ch = mt * 16 + q + 8 * hi;
                        int px = warp_n * 32 + nt * 8 + 2 * kl;
                        float2 v2 = make_float2(acc[mt][nt][hi * 2], acc[mt][nt][hi * 2 + 1]);
                        *(float2*)&stage[ch][px] = v2;
                    }
        }
        __syncthreads();
#pragma unroll
        for (int it = 0; it < 8; ++it) {
            int g = tid + it * 256;
            int ch = g >> 5;
            int f  = g & 31;
            int c  = c0 + h * 64 + ch;
            size_t gi = (((size_t)(b * C_IN + c)) * HWSZ + hw0) / 4 + f;
            float4 s = *(float4*)&stage[ch][f * 4];
            float4 xv = ((const float4*)x)[gi];
            float bb = b_back[c];
            float4 o4;
            o4.x = xv.x + bb + s.x;
            o4.y = xv.y + bb + s.y;
            o4.z = xv.z + bb + s.z;
            o4.w = xv.w + bb + s.w;
            ((float4*)out)[gi] = o4;
        }
    }
}

// ---------------------------------------------------------------------------
extern "C" void kernel_launch(void* const* d_in, const int* in_sizes, int n_in,
                              void* d_out, int out_size)
{
    const float* x       = (const float*)d_in[0];
    const float* w_theta = (const float*)d_in[1];
    const float* b_theta = (const float*)d_in[2];
    const float* w_phi   = (const float*)d_in[3];
    const float* b_phi   = (const float*)d_in[4];
    const float* w_g     = (const float*)d_in[5];
    const float* b_g     = (const float*)d_in[6];
    const float* w_back  = (const float*)d_in[7];
    const float* b_back  = (const float*)d_in[8];
    float* out = (float*)d_out;

    cvt_weights<<<128, 256>>>(w_theta, w_phi, w_g, w_back);

    dim3 g1(P_TOT / 128, 3, 1);
    pass1_gemm<<<g1, 256>>>(x, b_theta, b_phi, b_g);

    pass2_attn<<<P_TOT / 8, 256>>>();

    dim3 g3(P_TOT / 128, 2, 1);
    pass3_gemm<<<g3, 256>>>(x, b_back, out);
}

// round 5
// speedup vs baseline: 1.2495x; 1.1013x over previous
#include <cuda_runtime.h>
#include <math.h>
#include <stdint.h>

// Problem constants
#define HH 96
#define WWID 96
#define HWSZ (HH * WWID)          // 9216
#define BATCH 8
#define P_TOT (BATCH * HWSZ)      // 73728 pixels
#define C_IN 256
#define C_O 128

// Scratch (device globals — allocation-free per harness rules)
__device__ __align__(16) float g_theta[(size_t)P_TOT * C_O];
__device__ __align__(16) float g_phi  [(size_t)P_TOT * C_O];
__device__ __align__(16) float g_g    [(size_t)P_TOT * C_O];
__device__ __align__(16) float g_wa   [(size_t)P_TOT * C_O];   // stored tf32-rounded
__device__ __align__(16) float g_w3   [3 * C_O * C_IN];        // tf32 w_theta|w_phi|w_g
__device__ __align__(16) float g_wb   [C_IN * C_O];            // tf32 w_back
__device__ float g_tnorm[P_TOT];
__device__ float g_pnorm[P_TOT];

__device__ __forceinline__ uint32_t f2tf32(float x) {
    uint32_t r;
    asm("cvt.rna.tf32.f32 %0, %1;" : "=r"(r) : "f"(x));
    return r;
}

__device__ __forceinline__ void mma_tf32(float c[4],
                                         uint32_t a0, uint32_t a1, uint32_t a2, uint32_t a3,
                                         uint32_t b0, uint32_t b1) {
    asm volatile(
        "mma.sync.aligned.m16n8k8.row.col.f32.tf32.tf32.f32 "
        "{%0,%1,%2,%3},{%4,%5,%6,%7},{%8,%9},{%0,%1,%2,%3};"
        : "+f"(c[0]), "+f"(c[1]), "+f"(c[2]), "+f"(c[3])
        : "r"(a0), "r"(a1), "r"(a2), "r"(a3), "r"(b0), "r"(b1));
}

__device__ __forceinline__ void ldsm_x4(uint32_t& r0, uint32_t& r1, uint32_t& r2, uint32_t& r3,
                                        uint32_t addr) {
    asm volatile("ldmatrix.sync.aligned.m8n8.x4.shared.b16 {%0,%1,%2,%3}, [%4];"
                 : "=r"(r0), "=r"(r1), "=r"(r2), "=r"(r3) : "r"(addr));
}

__device__ __forceinline__ void ldsm_x2(uint32_t& r0, uint32_t& r1, uint32_t addr) {
    asm volatile("ldmatrix.sync.aligned.m8n8.x2.shared.b16 {%0,%1}, [%2];"
                 : "=r"(r0), "=r"(r1) : "r"(addr));
}

#define CP16_CA(dst, src) \
    asm volatile("cp.async.ca.shared.global [%0], [%1], 16;" :: "r"(dst), "l"(src))
#define CP16_CG(dst, src) \
    asm volatile("cp.async.cg.shared.global [%0], [%1], 16;" :: "r"(dst), "l"(src))
#define CP_COMMIT() asm volatile("cp.async.commit_group;")
#define CP_WAIT2()  asm volatile("cp.async.wait_group 2;")

// ---------------------------------------------------------------------------
// Setup: tf32-round all weights once.
// ---------------------------------------------------------------------------
__global__ void cvt_weights(const float* __restrict__ wt, const float* __restrict__ wp,
                            const float* __restrict__ wg, const float* __restrict__ wb)
{
    int i = blockIdx.x * 256 + threadIdx.x;      // 0 .. 32767
    g_w3[i]         = __uint_as_float(f2tf32(wt[i]));
    g_w3[32768 + i] = __uint_as_float(f2tf32(wp[i]));
    g_w3[65536 + i] = __uint_as_float(f2tf32(wg[i]));
    g_wb[i]         = __uint_as_float(f2tf32(wb[i]));
}

// ---------------------------------------------------------------------------
// Pass 1 (tensor, 4-stage cp.async): theta/phi/g = W(128x256)@x + bias.
// grid = (3, 576): wsel fastest -> 3 co-resident blocks share the x tile in L2.
// Norms of theta/phi computed in the epilogue (full channel dim in-block).
// dyn smem: 4*(2560+2176) + 128 = 19072 floats.
// ---------------------------------------------------------------------------
__global__ __launch_bounds__(256, 2) void pass1_gemm(
    const float* __restrict__ x,
    const float* __restrict__ b_theta, const float* __restrict__ b_phi,
    const float* __restrict__ b_g)
{
    extern __shared__ __align__(16) float sm[];
    float* As = sm;                    // [4][128][20]
    float* Bs = sm + 4 * 2560;         // [4][16][136]
    float (*stage)[68] = (float(*)[68])sm;
    float* part = sm + 18944;          // [128] per-px sum of squares

    const int tid = threadIdx.x;
    const int lane = tid & 31;
    const int warp = tid >> 5;
    const int warp_m = warp >> 2;
    const int warp_n = warp & 3;
    const int q = lane >> 2;
    const int kl = lane & 3;

    const int wsel = blockIdx.x;
    const int p0 = blockIdx.y * 128;
    const int b = p0 / HWSZ;
    const int hw0 = p0 % HWSZ;

    const float* wsrc = g_w3 + wsel * 32768;
    const float* bias = (wsel == 0) ? b_theta : ((wsel == 1) ? b_phi : b_g);
    float* outp       = (wsel == 0) ? g_theta : ((wsel == 1) ? g_phi : g_g);

    float acc[4][4][4];
#pragma unroll
    for (int mt = 0; mt < 4; ++mt)
#pragma unroll
        for (int nt = 0; nt < 4; ++nt)
#pragma unroll
            for (int i = 0; i < 4; ++i) acc[mt][nt][i] = 0.f;

    const int am   = tid >> 1;
    const int akq0 = (tid & 1) * 2;
    const int bk   = tid >> 4;
    const int bpq0 = (tid & 15) * 2;

    const uint32_t as_base = (uint32_t)__cvta_generic_to_shared(As);
    const uint32_t bs_base = (uint32_t)__cvta_generic_to_shared(Bs);
    const uint32_t a_dst0 = as_base + 4u * (uint32_t)(am * 20 + akq0 * 4);
    const uint32_t b_dst0 = bs_base + 4u * (uint32_t)(bk * 136 + bpq0 * 4);
    const float* a_src0 = wsrc + am * C_IN + akq0 * 4;
    const float* b_src0 = x + (size_t)(b * C_IN + bk) * HWSZ + hw0 + bpq0 * 4;

    const uint32_t a_frag = as_base + 4u * ((uint32_t)(warp_m * 64 + (lane & 15)) * 20u
                                            + (uint32_t)(lane >> 4) * 4u);

#define P1_ISSUE(buf, k0) do { \
    const float* as_ = a_src0 + (k0); \
    uint32_t ad_ = a_dst0 + (uint32_t)(buf) * 10240u; \
    CP16_CA(ad_,      as_); \
    CP16_CA(ad_ + 16, as_ + 4); \
    const float* bs_ = b_src0 + (size_t)(k0) * HWSZ; \
    uint32_t bd_ = b_dst0 + (uint32_t)(buf) * 8704u; \
    CP16_CG(bd_,      bs_); \
    CP16_CG(bd_ + 16, bs_ + 4); \
} while (0)

    P1_ISSUE(0, 0);  CP_COMMIT();
    P1_ISSUE(1, 16); CP_COMMIT();
    P1_ISSUE(2, 32); CP_COMMIT();

#pragma unroll 4
    for (int kt = 0; kt < 16; ++kt) {
        const int buf = kt & 3;
        CP_WAIT2();
        __syncthreads();
        if (kt + 3 < 16) P1_ISSUE((kt + 3) & 3, (kt + 3) * 16);
        CP_COMMIT();

#pragma unroll
        for (int ks = 0; ks < 16; ks += 8) {
            uint32_t af[4][4];
#pragma unroll
            for (int mt = 0; mt < 4; ++mt)
                ldsm_x4(af[mt][0], af[mt][1], af[mt][2], af[mt][3],
                        a_frag + (uint32_t)buf * 10240u + (uint32_t)mt * 1280u + (uint32_t)ks * 4u);
            uint32_t bf[4][2];
            const int kq = ks + kl;
#pragma unroll
            for (int nt = 0; nt < 4; ++nt) {
                int pc = warp_n * 32 + nt * 8 + q;
                bf[nt][0] = __float_as_uint(Bs[buf * 2176 + kq * 136 + pc]);
                bf[nt][1] = __float_as_uint(Bs[buf * 2176 + (kq + 4) * 136 + pc]);
            }
#pragma unroll
            for (int mt = 0; mt < 4; ++mt)
#pragma unroll
                for (int nt = 0; nt < 4; ++nt)
                    mma_tf32(acc[mt][nt], af[mt][0], af[mt][1], af[mt][2], af[mt][3],
                             bf[nt][0], bf[nt][1]);
        }
        __syncthreads();
    }
#undef P1_ISSUE

    float bias_v[4][2];
#pragma unroll
    for (int mt = 0; mt < 4; ++mt)
#pragma unroll
        for (int hi = 0; hi < 2; ++hi)
            bias_v[mt][hi] = bias[warp_m * 64 + mt * 16 + q + hi * 8];

    if (tid < 128) part[tid] = 0.f;

    // Epilogue: stage [px][64ch], coalesced stores + fused norm reduction
#pragma unroll
    for (int h = 0; h < 2; ++h) {
        __syncthreads();
        if (warp_m == h) {
#pragma unroll
            for (int mt = 0; mt < 4; ++mt)
#pragma unroll
                for (int nt = 0; nt < 4; ++nt)
#pragma unroll
                    for (int i = 0; i < 4; ++i) {
                        int px = warp_n * 32 + nt * 8 + 2 * kl + (i & 1);
                        int ch = mt * 16 + q + 8 * (i >> 1);
                        stage[px][ch] = acc[mt][nt][i] + bias_v[mt][i >> 1];
                    }
        }
        __syncthreads();
#pragma unroll
        for (int it = 0; it < 8; ++it) {
            int g = tid + it * 256;
            int px = g >> 4;
            int f  = g & 15;
            float4 v = *(float4*)&stage[px][f * 4];
            ((float4*)outp)[(size_t)(p0 + px) * 32 + h * 16 + f] = v;
            if (wsel < 2) {
                float sq = v.x * v.x + v.y * v.y + v.z * v.z + v.w * v.w;
                sq += __shfl_xor_sync(0xffffffffu, sq, 1);
                sq += __shfl_xor_sync(0xffffffffu, sq, 2);
                sq += __shfl_xor_sync(0xffffffffu, sq, 4);
                sq += __shfl_xor_sync(0xffffffffu, sq, 8);
                if (f == 0) part[px] += sq;   // same thread owns px across h: no race
            }
        }
    }
    __syncthreads();
    if (wsel < 2 && tid < 128) {
        float* np = (wsel == 0) ? g_tnorm : g_pnorm;
        np[p0 + tid] = sqrtf(part[tid]);
    }
}

// ---------------------------------------------------------------------------
// Pass 2: per-pixel 3x3 cosine-sim softmax + weighted avg of g (warp/pixel).
// Norms precomputed in pass1: only the dot-product shfl chain remains.
// ---------------------------------------------------------------------------
__global__ __launch_bounds__(256) void pass2_attn()
{
    const int warp = threadIdx.x >> 5;
    const int lane = threadIdx.x & 31;
    const int p = blockIdx.x * 8 + warp;
    const int b  = p / HWSZ;
    const int hw = p % HWSZ;
    const int h = hw / WWID;
    const int w = hw % WWID;

    const float4* th4 = (const float4*)g_theta;
    const float4* ph4 = (const float4*)g_phi;
    const float4* gg4 = (const float4*)g_g;

    float4 th = th4[(size_t)p * 32 + lane];
    float tn = g_tnorm[p];

    int pn[9];
    float sc[9];
#pragma unroll
    for (int n = 0; n < 9; ++n) {
        int di = n / 3 - 1, dj = n % 3 - 1;
        int hh = min(max(h + di, 0), HH - 1);
        int wn = min(max(w + dj, 0), WWID - 1);
        pn[n] = b * HWSZ + hh * WWID + wn;
        float4 ph = ph4[(size_t)pn[n] * 32 + lane];
        float d = th.x * ph.x + th.y * ph.y + th.z * ph.z + th.w * ph.w;
#pragma unroll
        for (int off = 16; off; off >>= 1)
            d += __shfl_xor_sync(0xffffffffu, d, off);
        float den = fmaxf(tn * g_pnorm[pn[n]], 1e-8f);
        sc[n] = d / den;
    }
    // softmax over 9 (scores bounded in [-1,1]: no max-shift needed)
    float s = 0.f;
#pragma unroll
    for (int n = 0; n < 9; ++n) { sc[n] = __expf(sc[n]); s += sc[n]; }
    float inv = 1.f / s;

    float4 acc = make_float4(0.f, 0.f, 0.f, 0.f);
#pragma unroll
    for (int n = 0; n < 9; ++n) {
        float a = sc[n] * inv;
        float4 gv = gg4[(size_t)pn[n] * 32 + lane];
        acc.x += a * gv.x; acc.y += a * gv.y;
        acc.z += a * gv.z; acc.w += a * gv.w;
    }
    uint4 o;
    o.x = f2tf32(acc.x); o.y = f2tf32(acc.y);
    o.z = f2tf32(acc.z); o.w = f2tf32(acc.w);
    ((uint4*)g_wa)[(size_t)p * 32 + lane] = o;
}

// ---------------------------------------------------------------------------
// Pass 3 (tensor, 4-stage cp.async): out = x + W_back(256x128)@wa + b_back.
// dyn smem: 4*2560*2 = 20480 floats.
// ---------------------------------------------------------------------------
__global__ __launch_bounds__(256, 2) void pass3_gemm(
    const float* __restrict__ x,
    const float* __restrict__ b_back,
    float* __restrict__ out)
{
    extern __shared__ __align__(16) float sm[];
    float* As = sm;                    // [4][128][20]
    float* Bs = sm + 4 * 2560;         // [4][128][20]
    float (*stage)[132] = (float(*)[132])sm;

    const int tid = threadIdx.x;
    const int lane = tid & 31;
    const int warp = tid >> 5;
    const int warp_m = warp >> 2;
    const int warp_n = warp & 3;
    const int q = lane >> 2;
    const int kl = lane & 3;

    const int p0 = blockIdx.x * 128;
    const int b = p0 / HWSZ;
    const int hw0 = p0 % HWSZ;
    const int c0 = blockIdx.y * 128;

    float acc[4][4][4];
#pragma unroll
    for (int mt = 0; mt < 4; ++mt)
#pragma unroll
        for (int nt = 0; nt < 4; ++nt)
#pragma unroll
            for (int i = 0; i < 4; ++i) acc[mt][nt][i] = 0.f;

    const int am   = tid >> 1;
    const int akq0 = (tid & 1) * 2;

    const uint32_t as_base = (uint32_t)__cvta_generic_to_shared(As);
    const uint32_t bs_base = (uint32_t)__cvta_generic_to_shared(Bs);
    const uint32_t a_dst0 = as_base + 4u * (uint32_t)(am * 20 + akq0 * 4);
    const uint32_t b_dst0 = bs_base + 4u * (uint32_t)(am * 20 + akq0 * 4);
    const float* a_src0 = g_wb + (size_t)(c0 + am) * C_O + akq0 * 4;
    const float* b_src0 = g_wa + (size_t)(p0 + am) * C_O + akq0 * 4;

    const uint32_t a_frag = as_base + 4u * ((uint32_t)(warp_m * 64 + (lane & 15)) * 20u
                                            + (uint32_t)(lane >> 4) * 4u);
    const uint32_t b_frag = bs_base + 4u * ((uint32_t)(warp_n * 32 + (lane & 7)) * 20u
                                            + (uint32_t)((lane >> 3) & 1) * 4u);

#define P3_ISSUE(buf, k0) do { \
    const float* as_ = a_src0 + (k0); \
    uint32_t ad_ = a_dst0 + (uint32_t)(buf) * 10240u; \
    CP16_CA(ad_,      as_); \
    CP16_CA(ad_ + 16, as_ + 4); \
    const float* bs_ = b_src0 + (k0); \
    uint32_t bd_ = b_dst0 + (uint32_t)(buf) * 10240u; \
    CP16_CG(bd_,      bs_); \
    CP16_CG(bd_ + 16, bs_ + 4); \
} while (0)

    P3_ISSUE(0, 0);  CP_COMMIT();
    P3_ISSUE(1, 16); CP_COMMIT();
    P3_ISSUE(2, 32); CP_COMMIT();

#pragma unroll 4
    for (int kt = 0; kt < 8; ++kt) {
        const int buf = kt & 3;
        CP_WAIT2();
        __syncthreads();
        if (kt + 3 < 8) P3_ISSUE((kt + 3) & 3, (kt + 3) * 16);
        CP_COMMIT();

#pragma unroll
        for (int ks = 0; ks < 16; ks += 8) {
            uint32_t af[4][4];
#pragma unroll
            for (int mt = 0; mt < 4; ++mt)
                ldsm_x4(af[mt][0], af[mt][1], af[mt][2], af[mt][3],
                        a_frag + (uint32_t)buf * 10240u + (uint32_t)mt * 1280u + (uint32_t)ks * 4u);
            uint32_t bf[4][2];
#pragma unroll
            for (int nt = 0; nt < 4; ++nt)
                ldsm_x2(bf[nt][0], bf[nt][1],
                        b_frag + (uint32_t)buf * 10240u + (uint32_t)nt * 640u + (uint32_t)ks * 4u);
#pragma unroll
            for (int mt = 0; mt < 4; ++mt)
#pragma unroll
                for (int nt = 0; nt < 4; ++nt)
                    mma_tf32(acc[mt][nt], af[mt][0], af[mt][1], af[mt][2], af[mt][3],
                             bf[nt][0], bf[nt][1]);
        }
        __syncthreads();
    }
#undef P3_ISSUE

    // Epilogue: stage [ch][px], then coalesced residual-add + store
#pragma unroll
    for (int h = 0; h < 2; ++h) {
        __syncthreads();
        if (warp_m == h) {
#pragma unroll
            for (int mt = 0; mt < 4; ++mt)
#pragma unroll
                for (int nt = 0; nt < 4; ++nt)
#pragma unroll
                    for (int hi = 0; hi < 2; ++hi) {
                        int ch = mt * 16 + q + 8 * hi;
                        int px = warp_n * 32 + nt * 8 + 2 * kl;
                        float2 v2 = make_float2(acc[mt][nt][hi * 2], acc[mt][nt][hi * 2 + 1]);
                        *(float2*)&stage[ch][px] = v2;
                    }
        }
        __syncthreads();
#pragma unroll
        for (int it = 0; it < 8; ++it) {
            int g = tid + it * 256;
            int ch = g >> 5;
            int f  = g & 31;
            int c  = c0 + h * 64 + ch;
            size_t gi = (((size_t)(b * C_IN + c)) * HWSZ + hw0) / 4 + f;
            float4 s = *(float4*)&stage[ch][f * 4];
            float4 xv = ((const float4*)x)[gi];
            float bb = b_back[c];
            float4 o4;
            o4.x = xv.x + bb + s.x;
            o4.y = xv.y + bb + s.y;
            o4.z = xv.z + bb + s.z;
            o4.w = xv.w + bb + s.w;
            ((float4*)out)[gi] = o4;
        }
    }
}

// ---------------------------------------------------------------------------
extern "C" void kernel_launch(void* const* d_in, const int* in_sizes, int n_in,
                              void* d_out, int out_size)
{
    const float* x       = (const float*)d_in[0];
    const float* w_theta = (const float*)d_in[1];
    const float* b_theta = (const float*)d_in[2];
    const float* w_phi   = (const float*)d_in[3];
    const float* b_phi   = (const float*)d_in[4];
    const float* w_g     = (const float*)d_in[5];
    const float* b_g     = (const float*)d_in[6];
    const float* w_back  = (const float*)d_in[7];
    const float* b_back  = (const float*)d_in[8];
    float* out = (float*)d_out;

    const int p1_smem = 19072 * 4;   // 76288 B
    const int p3_smem = 20480 * 4;   // 81920 B
    cudaFuncSetAttribute(pass1_gemm, cudaFuncAttributeMaxDynamicSharedMemorySize, p1_smem);
    cudaFuncSetAttribute(pass3_gemm, cudaFuncAttributeMaxDynamicSharedMemorySize, p3_smem);

    cvt_weights<<<128, 256>>>(w_theta, w_phi, w_g, w_back);

    dim3 g1(3, P_TOT / 128, 1);
    pass1_gemm<<<g1, 256, p1_smem>>>(x, b_theta, b_phi, b_g);

    pass2_attn<<<P_TOT / 8, 256>>>();

    dim3 g3(P_TOT / 128, 2, 1);
    pass3_gemm<<<g3, 256, p3_smem>>>(x, b_back, out);
}